// round 4
// baseline (speedup 1.0000x reference)
#include <cuda_runtime.h>

#define NB 256
#define NT 96
#define ND 32
#define NH 128
#define NOUT 32
#define NF 24
#define BC 64
#define NCTA 128
#define NTHR 512

#define HS2 129   // ull stride for hdup rows: lane stride 258 words = 2 mod 32 (conflict-free LDS.64)
#define GSS 130   // float stride for gs rows

#define F_OFS 0
#define F_CNT (NB*NF*NOUT)
#define A_OFS F_CNT
#define A_CNT (NB*NT*ND)
#define B_OFS (A_OFS + A_CNT)
#define B_CNT (NB*NF*ND)
#define O_OFS (B_OFS + B_CNT)

typedef unsigned long long ull;

// ------------- scratch (no allocs allowed) -------------
__device__ float g_h[ND*NB*NH];
__device__ float g_c[ND*NB*NH];
__device__ float g_gn[ND*NB*NH];
__device__ float g_den[NB*ND];
__device__ float g_mu[NB*ND*NOUT];
__device__ float g_bt[NB*ND];

struct EncSmem {
    ull   hdup[BC*HS2];   // h duplicated into both f32x2 lanes, padded rows
    float gs[BC*GSS];     // g_n staging, padded rows
    float Fa_s[NH];
    float xs[BC];
    float es[BC];
    float den_s[BC];
};

// ------------- packed f32x2 helpers -------------
__device__ __forceinline__ ull pack2(float lo, float hi) {
    ull r;
    asm("mov.b64 %0, {%1, %2};" : "=l"(r)
        : "r"(__float_as_uint(lo)), "r"(__float_as_uint(hi)));
    return r;
}
__device__ __forceinline__ ull dup2(float v) {
    ull r; unsigned u = __float_as_uint(v);
    asm("mov.b64 %0, {%1, %1};" : "=l"(r) : "r"(u));
    return r;
}
__device__ __forceinline__ void unpack2(ull p, float &lo, float &hi) {
    unsigned a, b;
    asm("mov.b64 {%0, %1}, %2;" : "=r"(a), "=r"(b) : "l"(p));
    lo = __uint_as_float(a); hi = __uint_as_float(b);
}
__device__ __forceinline__ void fma2(ull &acc, ull a, ull b) {
    asm("fma.rn.f32x2 %0, %1, %2, %0;" : "+l"(acc) : "l"(a), "l"(b));
}

__device__ __forceinline__ float sigf(float x) {
    return __fdividef(1.f, 1.f + __expf(-x));
}
__device__ __forceinline__ float tanhfast(float x) {
    float e = __expf(-2.f * x);
    return __fdividef(1.f - e, 1.f + e);
}

// ------------- one gate GEMM -------------
// thread: row r (0..63), cols c0..c0+15. W access is warp-uniform (broadcast).
// acc[p] = cols (c0+2p, c0+2p+1).
__device__ __forceinline__ void gate_gemm(
    const float* __restrict__ Wd, const float* __restrict__ Ud,
    const float* __restrict__ bd, const ull* __restrict__ hrow,
    float xv, int c0, ull acc[8])
{
    const float4* up = (const float4*)(Ud + c0);
    const float4* vp = (const float4*)(bd + c0);
#pragma unroll
    for (int q = 0; q < 4; ++q) {
        float4 u = up[q], v = vp[q];
        acc[q*2+0] = pack2(fmaf(xv,u.x,v.x), fmaf(xv,u.y,v.y));
        acc[q*2+1] = pack2(fmaf(xv,u.z,v.z), fmaf(xv,u.w,v.w));
    }
    const float* wp = Wd + c0;
#pragma unroll 4
    for (int k = 0; k < NH; ++k) {
        ull h = hrow[k];
        const ulonglong2* w2 = (const ulonglong2*)wp;
        ulonglong2 wa = w2[0], wb = w2[1], wc = w2[2], wd2 = w2[3];
        wp += NH;
        fma2(acc[0], h, wa.x); fma2(acc[1], h, wa.y);
        fma2(acc[2], h, wb.x); fma2(acc[3], h, wb.y);
        fma2(acc[4], h, wc.x); fma2(acc[5], h, wc.y);
        fma2(acc[6], h, wd2.x); fma2(acc[7], h, wd2.y);
    }
}

// ------------- full LSTM cell for this thread's 16 elements -------------
__device__ __forceinline__ void cell_step(
    const float* __restrict__ Wjd, const float* __restrict__ Wid,
    const float* __restrict__ Wfd, const float* __restrict__ Wod,
    const float* __restrict__ Ujd, const float* __restrict__ Uid,
    const float* __restrict__ Ufd, const float* __restrict__ Uod,
    const float* __restrict__ bjd, const float* __restrict__ bid,
    const float* __restrict__ bfd, const float* __restrict__ bod,
    const ull* __restrict__ hd, const float* __restrict__ xs,
    int c0, int r, float* c, float* h2)
{
    const ull* hrow = hd + (size_t)r * HS2;
    float xv = xs[r];
    ull acc[8];
    gate_gemm(Wjd, Ujd, bjd, hrow, xv, c0, acc);     // j
#pragma unroll
    for (int e = 0; e < 8; ++e) {
        float lo, hi; unpack2(acc[e], lo, hi);
        h2[e*2] = tanhfast(lo); h2[e*2+1] = tanhfast(hi);
    }
    gate_gemm(Wid, Uid, bid, hrow, xv, c0, acc);     // i  (h2 <- i*j)
#pragma unroll
    for (int e = 0; e < 8; ++e) {
        float lo, hi; unpack2(acc[e], lo, hi);
        h2[e*2] *= sigf(lo); h2[e*2+1] *= sigf(hi);
    }
    gate_gemm(Wfd, Ufd, bfd, hrow, xv, c0, acc);     // f  (c <- c*f + i*j)
#pragma unroll
    for (int e = 0; e < 8; ++e) {
        float lo, hi; unpack2(acc[e], lo, hi);
        c[e*2]   = fmaf(c[e*2],   sigf(lo), h2[e*2]);
        c[e*2+1] = fmaf(c[e*2+1], sigf(hi), h2[e*2+1]);
    }
    gate_gemm(Wod, Uod, bod, hrow, xv, c0, acc);     // o  (h2 <- o*tanh(c))
#pragma unroll
    for (int e = 0; e < 8; ++e) {
        float lo, hi; unpack2(acc[e], lo, hi);
        h2[e*2]   = sigf(lo) * tanhfast(c[e*2]);
        h2[e*2+1] = sigf(hi) * tanhfast(c[e*2+1]);
    }
}

// ------------- mu / bt for next fc step (hdup = h, gs = g_n) -------------
__device__ __forceinline__ void compute_mu_bt(
    EncSmem* s, int d, int b0, int tid,
    const float* __restrict__ Phi_w, const float* __restrict__ Phi_b,
    const float* __restrict__ Fbw, const float* __restrict__ Fbb)
{
    int outc = tid & 31;
    int bg = tid >> 5;                      // 16 groups x 4 batch rows
    float acc[4];
    float pb = Phi_b[outc];
#pragma unroll
    for (int r = 0; r < 4; ++r) acc[r] = pb;
#pragma unroll 2
    for (int k = 0; k < NH; ++k) {
        float pg = Phi_w[k*NOUT + outc];
        float ph = Phi_w[(NH + k)*NOUT + outc];
#pragma unroll
        for (int r = 0; r < 4; ++r) {
            int b = bg*4 + r;
            float hv = *(const float*)&s->hdup[b*HS2 + k];   // low lane = h
            acc[r] = fmaf(s->gs[b*GSS + k], pg, acc[r]);
            acc[r] = fmaf(hv, ph, acc[r]);
        }
    }
#pragma unroll
    for (int r = 0; r < 4; ++r)
        g_mu[(((size_t)(b0 + bg*4 + r))*ND + d)*NOUT + outc] = acc[r];

    // bt: 8 threads per batch row, 16 k each over both halves
    {
        int b = tid >> 3;            // 0..63
        int seg = tid & 7;
        float a = 0.f;
        const float* hrow = (const float*)&s->hdup[b*HS2];
#pragma unroll
        for (int kk = 0; kk < 16; ++kk) {
            int k = seg*16 + kk;
            a = fmaf(s->gs[b*GSS + k], Fbw[k],      a);
            a = fmaf(hrow[2*k],        Fbw[NH + k], a);
        }
        a += __shfl_xor_sync(0xffffffffu, a, 1);
        a += __shfl_xor_sync(0xffffffffu, a, 2);
        a += __shfl_xor_sync(0xffffffffu, a, 4);
        if (seg == 0)
            g_bt[(size_t)(b0 + b)*ND + d] = __expf(tanhfast(a + Fbb[0]));
    }
}

// ================= encoder: 96 steps persistent =================
__global__ void __launch_bounds__(NTHR, 1) enc_kernel(
    const float* __restrict__ x,
    const float* __restrict__ Uj, const float* __restrict__ Ui,
    const float* __restrict__ Uf, const float* __restrict__ Uo,
    const float* __restrict__ Wj, const float* __restrict__ Wi,
    const float* __restrict__ Wf, const float* __restrict__ Wo,
    const float* __restrict__ bj, const float* __restrict__ bi_,
    const float* __restrict__ bf, const float* __restrict__ bo,
    const float* __restrict__ Fa, const float* __restrict__ Fab,
    const float* __restrict__ Phi_w, const float* __restrict__ Phi_b,
    const float* __restrict__ Fbw, const float* __restrict__ Fbb,
    float* __restrict__ out)
{
    extern __shared__ char smem_raw[];
    EncSmem* s = (EncSmem*)smem_raw;

    const int tid = threadIdx.x;
    const int d  = blockIdx.x >> 2;
    const int b0 = (blockIdx.x & 3) * BC;
    const int lane = tid & 31;
    const int w = tid >> 5;
    const int r  = (w >> 3) * 32 + lane;   // batch row 0..63
    const int c0 = (w & 7) * 16;           // column base

    const size_t dHH = (size_t)d * NH * NH;
    const float *Wjd = Wj + dHH, *Wid = Wi + dHH, *Wfd = Wf + dHH, *Wod = Wo + dHH;
    const float *Ujd = Uj + d*NH, *Uid = Ui + d*NH, *Ufd = Uf + d*NH, *Uod = Uo + d*NH;
    const float *bjd = bj + d*NH, *bid = bi_ + d*NH, *bfd = bf + d*NH, *bod = bo + d*NH;
    const float fab = Fab[d];

    for (int i = tid; i < BC*HS2; i += NTHR) s->hdup[i] = 0ull;
    if (tid < BC) s->den_s[tid] = 0.f;
    if (tid < NH) s->Fa_s[tid] = Fa[d*NH + tid];

    float c[16], num[16], h2[16];
#pragma unroll
    for (int i = 0; i < 16; ++i) { c[i] = 0.f; num[i] = 0.f; }
    __syncthreads();

    for (int t = 0; t < NT; ++t) {
        if (tid < BC) s->xs[tid] = x[((size_t)(b0 + tid)*NT + t)*ND + d];
        __syncthreads();

        cell_step(Wjd,Wid,Wfd,Wod, Ujd,Uid,Ufd,Uod, bjd,bid,bfd,bod,
                  s->hdup, s->xs, c0, r, c, h2);
        __syncthreads();                      // gemm reads of old h done

        {
#pragma unroll
            for (int cc = 0; cc < 8; ++cc)
                s->hdup[r*HS2 + c0 + 2*cc] = pack2(h2[2*cc], h2[2*cc]);
#pragma unroll
            for (int cc = 0; cc < 8; ++cc)
                s->hdup[r*HS2 + c0 + 2*cc + 1] = pack2(h2[2*cc+1], h2[2*cc+1]);
            size_t off = O_OFS + (((size_t)(b0 + r)*NT + t)*ND + d)*NH + c0;
            *(float4*)(out + off)      = make_float4(h2[0],h2[1],h2[2],h2[3]);
            *(float4*)(out + off + 4)  = make_float4(h2[4],h2[5],h2[6],h2[7]);
            *(float4*)(out + off + 8)  = make_float4(h2[8],h2[9],h2[10],h2[11]);
            *(float4*)(out + off + 12) = make_float4(h2[12],h2[13],h2[14],h2[15]);
        }
        __syncthreads();                      // new h visible

        // attention: 8 threads per batch row, shuffle reduce
        {
            int b = tid >> 3;                 // 0..63
            int seg = tid & 7;
            const float* hrow = (const float*)&s->hdup[b*HS2];
            float sa = 0.f;
#pragma unroll
            for (int kk = 0; kk < 16; ++kk) {
                int k = seg*16 + kk;
                sa = fmaf(hrow[2*k], s->Fa_s[k], sa);
            }
            sa += __shfl_xor_sync(0xffffffffu, sa, 1);
            sa += __shfl_xor_sync(0xffffffffu, sa, 2);
            sa += __shfl_xor_sync(0xffffffffu, sa, 4);
            if (seg == 0) {
                float e = __expf(tanhfast(sa + fab));
                s->es[b] = e;
                s->den_s[b] += e;
                out[A_OFS + ((size_t)(b0 + b)*NT + t)*ND + d] = e;  // normalized later
            }
        }
        __syncthreads();                      // es visible

        {
            float e = s->es[r];
#pragma unroll
            for (int cc = 0; cc < 16; ++cc)
                num[cc] = fmaf(e, h2[cc], num[cc]);
        }
    }

    // epilogue: g_n, den, h, c; then mu/bt for fc step 0
    {
        float inv = __fdividef(1.f, s->den_s[r]);
        size_t gofs = ((size_t)d*NB + b0 + r)*NH + c0;
#pragma unroll
        for (int cc = 0; cc < 16; ++cc) {
            float gn = num[cc] * inv;
            s->gs[r*GSS + c0 + cc] = gn;
            g_gn[gofs + cc] = gn;
            g_h[gofs + cc] = h2[cc];
            g_c[gofs + cc] = c[cc];
        }
    }
    if (tid < BC) g_den[(size_t)(b0 + tid)*ND + d] = s->den_s[tid];
    __syncthreads();

    compute_mu_bt(s, d, b0, tid, Phi_w, Phi_b, Fbw, Fbb);
}

// ================= alphas finalize =================
__global__ void alphas_fin_kernel(float* __restrict__ out) {
    int i = blockIdx.x * 256 + threadIdx.x;
    if (i >= A_CNT) return;
    int b = i / (NT*ND);
    int d = i & (ND-1);
    out[A_OFS + i] = __fdividef(out[A_OFS + i], g_den[(size_t)b*ND + d]);
}

// ================= fc step: fold reduce + cell + mu/bt =================
__global__ void __launch_bounds__(NTHR, 1) cellmu_kernel(
    int f, int last,
    const float* __restrict__ Uj, const float* __restrict__ Ui,
    const float* __restrict__ Uf, const float* __restrict__ Uo,
    const float* __restrict__ Wj, const float* __restrict__ Wi,
    const float* __restrict__ Wf, const float* __restrict__ Wo,
    const float* __restrict__ bj, const float* __restrict__ bi_,
    const float* __restrict__ bf, const float* __restrict__ bo,
    const float* __restrict__ Phi_w, const float* __restrict__ Phi_b,
    const float* __restrict__ Fbw, const float* __restrict__ Fbb,
    const float* __restrict__ proj_w, const float* __restrict__ proj_b,
    float* __restrict__ out)
{
    extern __shared__ char smem_raw[];
    EncSmem* s = (EncSmem*)smem_raw;

    const int tid = threadIdx.x;
    const int d  = blockIdx.x >> 2;
    const int b0 = (blockIdx.x & 3) * BC;
    const int lane = tid & 31;
    const int w = tid >> 5;
    const int r  = (w >> 3) * 32 + lane;
    const int c0 = (w & 7) * 16;

    // ---- phase 0: softmax over D, y, forecasts, betas, prev (-> xs) ----
    {
#pragma unroll
        for (int rr = 0; rr < 4; ++rr) {
            int b = w*4 + rr;
            float bt = g_bt[(size_t)(b0 + b)*ND + lane];
            float ssum = bt;
#pragma unroll
            for (int o = 16; o > 0; o >>= 1)
                ssum += __shfl_xor_sync(0xffffffffu, ssum, o);
            float beta = __fdividef(bt, ssum);
            out[B_OFS + ((size_t)(b0 + b)*NF + f)*ND + lane] = beta;

            float y = 0.f;
            const float* mup = g_mu + ((size_t)(b0 + b)*ND)*NOUT + lane;
#pragma unroll
            for (int d2 = 0; d2 < ND; ++d2)
                y = fmaf(__shfl_sync(0xffffffffu, beta, d2), mup[d2*NOUT], y);
            out[F_OFS + ((size_t)(b0 + b)*NF + f)*NOUT + lane] = y;

            float p = y * proj_w[lane*ND + d];
#pragma unroll
            for (int o = 16; o > 0; o >>= 1)
                p += __shfl_xor_sync(0xffffffffu, p, o);
            if (lane == 0) s->xs[b] = p + proj_b[d];
        }
    }
    if (last) return;

    // ---- load state into smem ----
    for (int i = tid; i < BC*NH; i += NTHR) {
        int b = i >> 7, k = i & 127;
        size_t gofs = ((size_t)d*NB + b0 + b)*NH + k;
        s->hdup[b*HS2 + k] = dup2(g_h[gofs]);
        s->gs[b*GSS + k]   = g_gn[gofs];
    }

    float c[16], h2[16];
    {
        size_t gofs = ((size_t)d*NB + b0 + r)*NH + c0;
#pragma unroll
        for (int q = 0; q < 4; ++q) {
            float4 cv = *(const float4*)(g_c + gofs + q*4);
            c[q*4+0]=cv.x; c[q*4+1]=cv.y; c[q*4+2]=cv.z; c[q*4+3]=cv.w;
        }
    }
    __syncthreads();

    const size_t dHH = (size_t)d * NH * NH;
    const float *Wjd = Wj + dHH, *Wid = Wi + dHH, *Wfd = Wf + dHH, *Wod = Wo + dHH;
    const float *Ujd = Uj + d*NH, *Uid = Ui + d*NH, *Ufd = Uf + d*NH, *Uod = Uo + d*NH;
    const float *bjd = bj + d*NH, *bid = bi_ + d*NH, *bfd = bf + d*NH, *bod = bo + d*NH;

    cell_step(Wjd,Wid,Wfd,Wod, Ujd,Uid,Ufd,Uod, bjd,bid,bfd,bod,
              s->hdup, s->xs, c0, r, c, h2);
    __syncthreads();

    {
        size_t gofs = ((size_t)d*NB + b0 + r)*NH + c0;
#pragma unroll
        for (int cc = 0; cc < 16; ++cc) {
            s->hdup[r*HS2 + c0 + cc] = dup2(h2[cc]);
            g_h[gofs + cc] = h2[cc];
            g_c[gofs + cc] = c[cc];
        }
    }
    __syncthreads();

    compute_mu_bt(s, d, b0, tid, Phi_w, Phi_b, Fbw, Fbb);
}

// ================= launch =================
extern "C" void kernel_launch(void* const* d_in, const int* in_sizes, int n_in,
                              void* d_out, int out_size) {
    const float* x    = (const float*)d_in[0];
    const float* Uj   = (const float*)d_in[1];
    const float* Ui   = (const float*)d_in[2];
    const float* Uf   = (const float*)d_in[3];
    const float* Uo   = (const float*)d_in[4];
    const float* Wj   = (const float*)d_in[5];
    const float* Wi   = (const float*)d_in[6];
    const float* Wf   = (const float*)d_in[7];
    const float* Wo   = (const float*)d_in[8];
    const float* bj   = (const float*)d_in[9];
    const float* bi   = (const float*)d_in[10];
    const float* bf   = (const float*)d_in[11];
    const float* bo   = (const float*)d_in[12];
    const float* Fa   = (const float*)d_in[13];
    const float* Fab  = (const float*)d_in[14];
    const float* Fbw  = (const float*)d_in[15];
    const float* Fbb  = (const float*)d_in[16];
    const float* Phw  = (const float*)d_in[17];
    const float* Phb  = (const float*)d_in[18];
    const float* prw  = (const float*)d_in[19];
    const float* prb  = (const float*)d_in[20];
    float* out = (float*)d_out;

    int smem = (int)sizeof(EncSmem);
    cudaFuncSetAttribute(enc_kernel,    cudaFuncAttributeMaxDynamicSharedMemorySize, smem);
    cudaFuncSetAttribute(cellmu_kernel, cudaFuncAttributeMaxDynamicSharedMemorySize, smem);

    enc_kernel<<<NCTA, NTHR, smem>>>(x, Uj,Ui,Uf,Uo, Wj,Wi,Wf,Wo, bj,bi,bf,bo,
                                     Fa, Fab, Phw, Phb, Fbw, Fbb, out);
    alphas_fin_kernel<<<(A_CNT + 255)/256, 256>>>(out);

    for (int f = 0; f < NF; ++f) {
        cellmu_kernel<<<NCTA, NTHR, smem>>>(f, (f == NF-1) ? 1 : 0,
                                            Uj,Ui,Uf,Uo, Wj,Wi,Wf,Wo,
                                            bj,bi,bf,bo, Phw, Phb, Fbw, Fbb,
                                            prw, prb, out);
    }
}

// round 5
// speedup vs baseline: 2.3383x; 2.3383x over previous
#include <cuda_runtime.h>

#define NB 256
#define NT 96
#define ND 32
#define NH 128
#define NOUT 32
#define NF 24
#define BC 64
#define NCTA 128
#define NTHR 512
#define HS2 129   // ull stride for hdup rows (conflict-free)

#define F_CNT (NB*NF*NOUT)
#define A_OFS F_CNT
#define A_CNT (NB*NT*ND)
#define B_OFS (A_OFS + A_CNT)
#define B_CNT (NB*NF*ND)
#define O_OFS (B_OFS + B_CNT)

typedef unsigned long long ull;

// ------------- scratch (no allocs allowed) -------------
__device__ float g_h[ND*NB*NH];
__device__ float g_c[ND*NB*NH];
__device__ float g_gn[ND*NB*NH];
__device__ float g_den[NB*ND];
__device__ float g_mu[NB*ND*NOUT];
__device__ float g_bt[NB*ND];

struct S {
    float Wt[2][4*32*128];   // double-buffered W tile: [gate][kk][col], 2 x 64KB
    ull   hdup[BC*HS2];      // h duplicated into both f32x2 lanes
    float Fa_s[NH];
    float xs[BC];
    float es[BC];
    float den_s[BC];
};

// ------------- packed f32x2 helpers -------------
__device__ __forceinline__ ull pack2(float lo, float hi) {
    ull r;
    asm("mov.b64 %0, {%1, %2};" : "=l"(r)
        : "r"(__float_as_uint(lo)), "r"(__float_as_uint(hi)));
    return r;
}
__device__ __forceinline__ ull dup2(float v) {
    ull r; unsigned u = __float_as_uint(v);
    asm("mov.b64 %0, {%1, %1};" : "=l"(r) : "r"(u));
    return r;
}
__device__ __forceinline__ void unpack2(ull p, float &lo, float &hi) {
    unsigned a, b;
    asm("mov.b64 {%0, %1}, %2;" : "=r"(a), "=r"(b) : "l"(p));
    lo = __uint_as_float(a); hi = __uint_as_float(b);
}
__device__ __forceinline__ void fma2(ull &acc, ull a, ull b) {
    asm("fma.rn.f32x2 %0, %1, %2, %0;" : "+l"(acc) : "l"(a), "l"(b));
}

__device__ __forceinline__ float sigf(float x) {
    return __fdividef(1.f, 1.f + __expf(-x));
}
__device__ __forceinline__ float tanhfast(float x) {
    float e = __expf(-2.f * x);
    return __fdividef(1.f - e, 1.f + e);
}

// ------------- cp.async helpers -------------
__device__ __forceinline__ void cp16(unsigned dst, const void* src) {
    asm volatile("cp.async.cg.shared.global [%0], [%1], 16;" :: "r"(dst), "l"(src));
}
__device__ __forceinline__ void cp_commit() {
    asm volatile("cp.async.commit_group;");
}
template<int N> __device__ __forceinline__ void cp_wait() {
    asm volatile("cp.async.wait_group %0;" :: "n"(N));
}

// stage one 64KB W tile (all 4 gates) into smem buffer at byte addr wtb.
// thread role: gate g = tid>>7, q = tid&127; 8 x 16B per thread, coalesced.
__device__ __forceinline__ void issue_tile(unsigned wtb, const float* __restrict__ gw,
                                           int tile, int q, int g) {
    unsigned dst = wtb + (unsigned)(g*4096 + q*4) * 4u;
    const float4* src = (const float4*)(gw + tile*4096) + q;
#pragma unroll
    for (int j = 0; j < 8; ++j)
        cp16(dst + j*2048u, src + j*128);
    cp_commit();
}

// compute one K tile: 32 kk, 4 gates, rows (lane, lane+32), cols c0..c0+7
__device__ __forceinline__ void compute_tile(const float* __restrict__ wt,
                                             const ull* __restrict__ h0p,
                                             const ull* __restrict__ h1p,
                                             int c0, ull* acc) {
#pragma unroll 2
    for (int kk = 0; kk < 32; ++kk) {
        ull h0 = h0p[kk], h1 = h1p[kk];
#pragma unroll
        for (int g = 0; g < 4; ++g) {
            const ulonglong2* wp = (const ulonglong2*)(wt + g*4096 + kk*128 + c0);
            ulonglong2 wa = wp[0], wb = wp[1];
            fma2(acc[g*8+0], h0, wa.x); fma2(acc[g*8+1], h0, wa.y);
            fma2(acc[g*8+2], h0, wb.x); fma2(acc[g*8+3], h0, wb.y);
            fma2(acc[g*8+4], h1, wa.x); fma2(acc[g*8+5], h1, wa.y);
            fma2(acc[g*8+6], h1, wb.x); fma2(acc[g*8+7], h1, wb.y);
        }
    }
}

#define INITG(gg, Up, Bp) { \
    float4 u0 = *(const float4*)((Up) + c0); float4 u1 = *(const float4*)((Up) + c0 + 4); \
    float4 v0 = *(const float4*)((Bp) + c0); float4 v1 = *(const float4*)((Bp) + c0 + 4); \
    acc[(gg)*8+0] = pack2(fmaf(xv0,u0.x,v0.x), fmaf(xv0,u0.y,v0.y)); \
    acc[(gg)*8+1] = pack2(fmaf(xv0,u0.z,v0.z), fmaf(xv0,u0.w,v0.w)); \
    acc[(gg)*8+2] = pack2(fmaf(xv0,u1.x,v1.x), fmaf(xv0,u1.y,v1.y)); \
    acc[(gg)*8+3] = pack2(fmaf(xv0,u1.z,v1.z), fmaf(xv0,u1.w,v1.w)); \
    acc[(gg)*8+4] = pack2(fmaf(xv1,u0.x,v0.x), fmaf(xv1,u0.y,v0.y)); \
    acc[(gg)*8+5] = pack2(fmaf(xv1,u0.z,v0.z), fmaf(xv1,u0.w,v0.w)); \
    acc[(gg)*8+6] = pack2(fmaf(xv1,u1.x,v1.x), fmaf(xv1,u1.y,v1.y)); \
    acc[(gg)*8+7] = pack2(fmaf(xv1,u1.z,v1.z), fmaf(xv1,u1.w,v1.w)); }

// ------------- full pipelined LSTM cell -------------
// result: h2[0..7] = row lane cols c0..c0+7, h2[8..15] = row lane+32. c likewise.
__device__ __forceinline__ void cell_pipe(
    S* s, unsigned wt0, unsigned wt1,
    const float* __restrict__ gw, int q, int g,
    const float* __restrict__ Ujd, const float* __restrict__ Uid,
    const float* __restrict__ Ufd, const float* __restrict__ Uod,
    const float* __restrict__ bjd, const float* __restrict__ bid,
    const float* __restrict__ bfd, const float* __restrict__ bod,
    int lane, int c0, float* c, float* h2)
{
    ull acc[32];
    issue_tile(wt0, gw, 0, q, g);
    const ull* h0b = s->hdup + (size_t)lane * HS2;
    const ull* h1b = s->hdup + (size_t)(lane + 32) * HS2;
#pragma unroll
    for (int t = 0; t < 4; ++t) {
        if (t < 3) issue_tile((t & 1) ? wt0 : wt1, gw, t + 1, q, g);
        if (t < 3) cp_wait<1>(); else cp_wait<0>();
        __syncthreads();
        if (t == 0) {
            float xv0 = s->xs[lane], xv1 = s->xs[lane + 32];
            INITG(0, Ujd, bjd); INITG(1, Uid, bid);
            INITG(2, Ufd, bfd); INITG(3, Uod, bod);
        }
        const float* wt = (t & 1) ? (const float*)(s->Wt[1]) : (const float*)(s->Wt[0]);
        compute_tile(wt, h0b + t*32, h1b + t*32, c0, acc);
        __syncthreads();
    }
    // activations: j=tanh, i/f/o=sigmoid; c' = c*f + i*j; h' = o*tanh(c')
#pragma unroll
    for (int e = 0; e < 8; ++e) {
        int ii = (e >> 2) * 8 + (e & 3) * 2;
        float jl, jh, il, ih, fl, fh, ol, oh;
        unpack2(acc[e],      jl, jh);
        unpack2(acc[8 + e],  il, ih);
        unpack2(acc[16 + e], fl, fh);
        unpack2(acc[24 + e], ol, oh);
        float cl = fmaf(c[ii],   sigf(fl), sigf(il) * tanhfast(jl));
        float ch = fmaf(c[ii+1], sigf(fh), sigf(ih) * tanhfast(jh));
        c[ii] = cl; c[ii+1] = ch;
        h2[ii]   = sigf(ol) * tanhfast(cl);
        h2[ii+1] = sigf(oh) * tanhfast(ch);
    }
}

// ------------- mu / bt for next fc step (hdup = h smem, g_n from global) -------------
__device__ __forceinline__ void compute_mu_bt(
    S* s, int d, int b0, int tid,
    const float* __restrict__ Phi_w, const float* __restrict__ Phi_b,
    const float* __restrict__ Fbw, const float* __restrict__ Fbb)
{
    int outc = tid & 31;
    int bg = tid >> 5;                      // 16 groups x 4 batch rows
    const float* gnb = g_gn + ((size_t)d*NB + b0 + bg*4)*NH;
    float acc[4];
    float pb = Phi_b[outc];
#pragma unroll
    for (int r = 0; r < 4; ++r) acc[r] = pb;
#pragma unroll 2
    for (int k = 0; k < NH; ++k) {
        float pg = Phi_w[k*NOUT + outc];
        float ph = Phi_w[(NH + k)*NOUT + outc];
#pragma unroll
        for (int r = 0; r < 4; ++r) {
            float hv = *(const float*)&s->hdup[(bg*4 + r)*HS2 + k];   // low lane = h
            acc[r] = fmaf(gnb[r*NH + k], pg, acc[r]);
            acc[r] = fmaf(hv, ph, acc[r]);
        }
    }
#pragma unroll
    for (int r = 0; r < 4; ++r)
        g_mu[(((size_t)(b0 + bg*4 + r))*ND + d)*NOUT + outc] = acc[r];

    // bt: 8 threads per batch row
    {
        int b = tid >> 3;            // 0..63
        int seg = tid & 7;
        const float* gnr = g_gn + ((size_t)d*NB + b0 + b)*NH;
        const float* hrow = (const float*)&s->hdup[b*HS2];
        float a = 0.f;
#pragma unroll
        for (int kk = 0; kk < 16; ++kk) {
            int k = seg*16 + kk;
            a = fmaf(gnr[k],    Fbw[k],      a);
            a = fmaf(hrow[2*k], Fbw[NH + k], a);
        }
        a += __shfl_xor_sync(0xffffffffu, a, 1);
        a += __shfl_xor_sync(0xffffffffu, a, 2);
        a += __shfl_xor_sync(0xffffffffu, a, 4);
        if (seg == 0)
            g_bt[(size_t)(b0 + b)*ND + d] = __expf(tanhfast(a + Fbb[0]));
    }
}

// ================= encoder: 96 steps persistent =================
__global__ void __launch_bounds__(NTHR, 1) enc_kernel(
    const float* __restrict__ x,
    const float* __restrict__ Uj, const float* __restrict__ Ui,
    const float* __restrict__ Uf, const float* __restrict__ Uo,
    const float* __restrict__ Wj, const float* __restrict__ Wi,
    const float* __restrict__ Wf, const float* __restrict__ Wo,
    const float* __restrict__ bj, const float* __restrict__ bi_,
    const float* __restrict__ bf, const float* __restrict__ bo,
    const float* __restrict__ Fa, const float* __restrict__ Fab,
    const float* __restrict__ Phi_w, const float* __restrict__ Phi_b,
    const float* __restrict__ Fbw, const float* __restrict__ Fbb,
    float* __restrict__ out)
{
    extern __shared__ char smem_raw[];
    S* s = (S*)smem_raw;

    const int tid = threadIdx.x;
    const int d  = blockIdx.x >> 2;
    const int b0 = (blockIdx.x & 3) * BC;
    const int lane = tid & 31;
    const int w = tid >> 5;
    const int c0 = w * 8;            // 16 warps x 8 cols = 128 cols
    const int q = tid & 127;
    const int g = tid >> 7;

    const size_t dHH = (size_t)d * NH * NH;
    const float* gw = (g == 0 ? Wj : g == 1 ? Wi : g == 2 ? Wf : Wo) + dHH;
    const float *Ujd = Uj + d*NH, *Uid = Ui + d*NH, *Ufd = Uf + d*NH, *Uod = Uo + d*NH;
    const float *bjd = bj + d*NH, *bid = bi_ + d*NH, *bfd = bf + d*NH, *bod = bo + d*NH;
    const float fab = Fab[d];

    unsigned wt0 = (unsigned)__cvta_generic_to_shared(s->Wt[0]);
    unsigned wt1 = (unsigned)__cvta_generic_to_shared(s->Wt[1]);

    for (int i = tid; i < BC*HS2; i += NTHR) s->hdup[i] = 0ull;
    if (tid < BC) s->den_s[tid] = 0.f;
    if (tid < NH) s->Fa_s[tid] = Fa[d*NH + tid];

    float c[16], num[16], h2[16];
#pragma unroll
    for (int i = 0; i < 16; ++i) { c[i] = 0.f; num[i] = 0.f; }
    __syncthreads();

    for (int t = 0; t < NT; ++t) {
        if (tid < BC) s->xs[tid] = x[((size_t)(b0 + tid)*NT + t)*ND + d];

        cell_pipe(s, wt0, wt1, gw, q, g, Ujd,Uid,Ufd,Uod, bjd,bid,bfd,bod,
                  lane, c0, c, h2);

        // write new h into hdup + outputs
        {
#pragma unroll
            for (int cc = 0; cc < 8; ++cc)
                s->hdup[lane*HS2 + c0 + cc] = dup2(h2[cc]);
#pragma unroll
            for (int cc = 0; cc < 8; ++cc)
                s->hdup[(lane+32)*HS2 + c0 + cc] = dup2(h2[8 + cc]);
            size_t off0 = O_OFS + (((size_t)(b0 + lane)*NT + t)*ND + d)*NH + c0;
            size_t off1 = O_OFS + (((size_t)(b0 + lane + 32)*NT + t)*ND + d)*NH + c0;
            *(float4*)(out + off0)     = make_float4(h2[0],h2[1],h2[2],h2[3]);
            *(float4*)(out + off0 + 4) = make_float4(h2[4],h2[5],h2[6],h2[7]);
            *(float4*)(out + off1)     = make_float4(h2[8],h2[9],h2[10],h2[11]);
            *(float4*)(out + off1 + 4) = make_float4(h2[12],h2[13],h2[14],h2[15]);
        }
        __syncthreads();

        // attention: 8 threads per batch row
        {
            int b = tid >> 3;
            int seg = tid & 7;
            const float* hrow = (const float*)&s->hdup[b*HS2];
            float sa = 0.f;
#pragma unroll
            for (int kk = 0; kk < 16; ++kk) {
                int k = seg*16 + kk;
                sa = fmaf(hrow[2*k], s->Fa_s[k], sa);
            }
            sa += __shfl_xor_sync(0xffffffffu, sa, 1);
            sa += __shfl_xor_sync(0xffffffffu, sa, 2);
            sa += __shfl_xor_sync(0xffffffffu, sa, 4);
            if (seg == 0) {
                float e = __expf(tanhfast(sa + fab));
                s->es[b] = e;
                s->den_s[b] += e;
                out[A_OFS + ((size_t)(b0 + b)*NT + t)*ND + d] = e;  // normalized later
            }
        }
        __syncthreads();

        {
            float e0 = s->es[lane], e1 = s->es[lane + 32];
#pragma unroll
            for (int cc = 0; cc < 8; ++cc) {
                num[cc]     = fmaf(e0, h2[cc],     num[cc]);
                num[8 + cc] = fmaf(e1, h2[8 + cc], num[8 + cc]);
            }
        }
    }

    // epilogue: g_n, den, h, c; then mu/bt for fc step 0
    {
        float inv0 = __fdividef(1.f, s->den_s[lane]);
        float inv1 = __fdividef(1.f, s->den_s[lane + 32]);
        size_t g0 = ((size_t)d*NB + b0 + lane)*NH + c0;
        size_t g1 = ((size_t)d*NB + b0 + lane + 32)*NH + c0;
#pragma unroll
        for (int cc = 0; cc < 8; ++cc) {
            g_gn[g0 + cc] = num[cc] * inv0;
            g_gn[g1 + cc] = num[8 + cc] * inv1;
            g_h[g0 + cc] = h2[cc];
            g_h[g1 + cc] = h2[8 + cc];
            g_c[g0 + cc] = c[cc];
            g_c[g1 + cc] = c[8 + cc];
        }
    }
    if (tid < BC) g_den[(size_t)(b0 + tid)*ND + d] = s->den_s[tid];
    __syncthreads();

    compute_mu_bt(s, d, b0, tid, Phi_w, Phi_b, Fbw, Fbb);
}

// ================= alphas finalize =================
__global__ void alphas_fin_kernel(float* __restrict__ out) {
    int i = blockIdx.x * 256 + threadIdx.x;
    if (i >= A_CNT) return;
    int b = i / (NT*ND);
    int d = i & (ND-1);
    out[A_OFS + i] = __fdividef(out[A_OFS + i], g_den[(size_t)b*ND + d]);
}

// ================= fc step: reduce + cell + mu/bt =================
__global__ void __launch_bounds__(NTHR, 1) cellmu_kernel(
    int f, int last,
    const float* __restrict__ Uj, const float* __restrict__ Ui,
    const float* __restrict__ Uf, const float* __restrict__ Uo,
    const float* __restrict__ Wj, const float* __restrict__ Wi,
    const float* __restrict__ Wf, const float* __restrict__ Wo,
    const float* __restrict__ bj, const float* __restrict__ bi_,
    const float* __restrict__ bf, const float* __restrict__ bo,
    const float* __restrict__ Phi_w, const float* __restrict__ Phi_b,
    const float* __restrict__ Fbw, const float* __restrict__ Fbb,
    const float* __restrict__ proj_w, const float* __restrict__ proj_b,
    float* __restrict__ out)
{
    extern __shared__ char smem_raw[];
    S* s = (S*)smem_raw;

    const int tid = threadIdx.x;
    const int d  = blockIdx.x >> 2;
    const int b0 = (blockIdx.x & 3) * BC;
    const int lane = tid & 31;
    const int w = tid >> 5;
    const int c0 = w * 8;
    const int q = tid & 127;
    const int g = tid >> 7;

    // ---- phase 0: softmax over D, y, forecasts, betas, prev (-> xs) ----
    {
#pragma unroll
        for (int rr = 0; rr < 4; ++rr) {
            int b = w*4 + rr;
            float bt = g_bt[(size_t)(b0 + b)*ND + lane];
            float ssum = bt;
#pragma unroll
            for (int o = 16; o > 0; o >>= 1)
                ssum += __shfl_xor_sync(0xffffffffu, ssum, o);
            float beta = __fdividef(bt, ssum);
            out[B_OFS + ((size_t)(b0 + b)*NF + f)*ND + lane] = beta;

            float y = 0.f;
            const float* mup = g_mu + ((size_t)(b0 + b)*ND)*NOUT + lane;
#pragma unroll
            for (int d2 = 0; d2 < ND; ++d2)
                y = fmaf(__shfl_sync(0xffffffffu, beta, d2), mup[d2*NOUT], y);
            out[((size_t)(b0 + b)*NF + f)*NOUT + lane] = y;

            float p = y * proj_w[lane*ND + d];
#pragma unroll
            for (int o = 16; o > 0; o >>= 1)
                p += __shfl_xor_sync(0xffffffffu, p, o);
            if (lane == 0) s->xs[b] = p + proj_b[d];
        }
    }
    if (last) return;

    // ---- load state ----
    for (int i = tid; i < BC*NH; i += NTHR) {
        int b = i >> 7, k = i & 127;
        s->hdup[b*HS2 + k] = dup2(g_h[((size_t)d*NB + b0 + b)*NH + k]);
    }

    float c[16], h2[16];
    {
        size_t g0 = ((size_t)d*NB + b0 + lane)*NH + c0;
        size_t g1 = ((size_t)d*NB + b0 + lane + 32)*NH + c0;
        float4 a0 = *(const float4*)(g_c + g0);
        float4 a1 = *(const float4*)(g_c + g0 + 4);
        float4 a2 = *(const float4*)(g_c + g1);
        float4 a3 = *(const float4*)(g_c + g1 + 4);
        c[0]=a0.x; c[1]=a0.y; c[2]=a0.z; c[3]=a0.w;
        c[4]=a1.x; c[5]=a1.y; c[6]=a1.z; c[7]=a1.w;
        c[8]=a2.x; c[9]=a2.y; c[10]=a2.z; c[11]=a2.w;
        c[12]=a3.x; c[13]=a3.y; c[14]=a3.z; c[15]=a3.w;
    }

    const size_t dHH = (size_t)d * NH * NH;
    const float* gw = (g == 0 ? Wj : g == 1 ? Wi : g == 2 ? Wf : Wo) + dHH;
    const float *Ujd = Uj + d*NH, *Uid = Ui + d*NH, *Ufd = Uf + d*NH, *Uod = Uo + d*NH;
    const float *bjd = bj + d*NH, *bid = bi_ + d*NH, *bfd = bf + d*NH, *bod = bo + d*NH;

    unsigned wt0 = (unsigned)__cvta_generic_to_shared(s->Wt[0]);
    unsigned wt1 = (unsigned)__cvta_generic_to_shared(s->Wt[1]);

    cell_pipe(s, wt0, wt1, gw, q, g, Ujd,Uid,Ufd,Uod, bjd,bid,bfd,bod,
              lane, c0, c, h2);

    {
        size_t g0 = ((size_t)d*NB + b0 + lane)*NH + c0;
        size_t g1 = ((size_t)d*NB + b0 + lane + 32)*NH + c0;
#pragma unroll
        for (int cc = 0; cc < 8; ++cc) {
            s->hdup[lane*HS2 + c0 + cc]      = dup2(h2[cc]);
            s->hdup[(lane+32)*HS2 + c0 + cc] = dup2(h2[8 + cc]);
            g_h[g0 + cc] = h2[cc];
            g_h[g1 + cc] = h2[8 + cc];
            g_c[g0 + cc] = c[cc];
            g_c[g1 + cc] = c[8 + cc];
        }
    }
    __syncthreads();

    compute_mu_bt(s, d, b0, tid, Phi_w, Phi_b, Fbw, Fbb);
}

// ================= launch =================
extern "C" void kernel_launch(void* const* d_in, const int* in_sizes, int n_in,
                              void* d_out, int out_size) {
    const float* x    = (const float*)d_in[0];
    const float* Uj   = (const float*)d_in[1];
    const float* Ui   = (const float*)d_in[2];
    const float* Uf   = (const float*)d_in[3];
    const float* Uo   = (const float*)d_in[4];
    const float* Wj   = (const float*)d_in[5];
    const float* Wi   = (const float*)d_in[6];
    const float* Wf   = (const float*)d_in[7];
    const float* Wo   = (const float*)d_in[8];
    const float* bj   = (const float*)d_in[9];
    const float* bi   = (const float*)d_in[10];
    const float* bf   = (const float*)d_in[11];
    const float* bo   = (const float*)d_in[12];
    const float* Fa   = (const float*)d_in[13];
    const float* Fab  = (const float*)d_in[14];
    const float* Fbw  = (const float*)d_in[15];
    const float* Fbb  = (const float*)d_in[16];
    const float* Phw  = (const float*)d_in[17];
    const float* Phb  = (const float*)d_in[18];
    const float* prw  = (const float*)d_in[19];
    const float* prb  = (const float*)d_in[20];
    float* out = (float*)d_out;

    int smem = (int)sizeof(S);
    cudaFuncSetAttribute(enc_kernel,    cudaFuncAttributeMaxDynamicSharedMemorySize, smem);
    cudaFuncSetAttribute(cellmu_kernel, cudaFuncAttributeMaxDynamicSharedMemorySize, smem);

    enc_kernel<<<NCTA, NTHR, smem>>>(x, Uj,Ui,Uf,Uo, Wj,Wi,Wf,Wo, bj,bi,bf,bo,
                                     Fa, Fab, Phw, Phb, Fbw, Fbb, out);
    alphas_fin_kernel<<<(A_CNT + 255)/256, 256>>>(out);

    for (int f = 0; f < NF; ++f) {
        cellmu_kernel<<<NCTA, NTHR, smem>>>(f, (f == NF-1) ? 1 : 0,
                                            Uj,Ui,Uf,Uo, Wj,Wi,Wf,Wo,
                                            bj,bi,bf,bo, Phw, Phb, Fbw, Fbb,
                                            prw, prb, out);
    }
}

// round 6
// speedup vs baseline: 2.5740x; 1.1008x over previous
#include <cuda_runtime.h>

#define NB 256
#define NT 96
#define ND 32
#define NH 128
#define NOUT 32
#define NF 24
#define BC 64
#define NCTA 128
#define NTHR 512
#define HS2 129   // ull stride for hdup rows (conflict-free LDS.64)
#define GST 130   // float stride for gn staging rows

#define F_CNT (NB*NF*NOUT)
#define A_OFS F_CNT
#define A_CNT (NB*NT*ND)
#define B_OFS (A_OFS + A_CNT)
#define O_OFS (B_OFS + NB*NF*ND)

typedef unsigned long long ull;

// ------------- scratch (no allocs allowed) -------------
__device__ float g_h[ND*NB*NH];
__device__ float g_c[ND*NB*NH];
__device__ float g_den[NB*ND];
__device__ float g_mug[NB*ND*NOUT];   // static part of mu
__device__ float g_btg[NB*ND];        // static part of bt argument
__device__ float g_mu2[2][NB*ND*NOUT];
__device__ float g_bt2[2][NB*ND];
__device__ unsigned g_cnt;
__device__ unsigned g_gen;

struct S {
    float Wt[2][4*32*128];   // double-buffered W tile [gate][kk][col], 2 x 64KB
    ull   hdup[BC*HS2];      // h duplicated into both f32x2 lanes
    float phi_s[NH*NOUT];    // Phi_w bottom half (h part)
    float fbw_s[NH];         // F_beta_w bottom half
    float Fa_s[NH];
    float xs[BC];
    float es[BC];
    float den_s[BC];
};

// ------------- packed f32x2 helpers -------------
__device__ __forceinline__ ull pack2(float lo, float hi) {
    ull r;
    asm("mov.b64 %0, {%1, %2};" : "=l"(r)
        : "r"(__float_as_uint(lo)), "r"(__float_as_uint(hi)));
    return r;
}
__device__ __forceinline__ ull dup2(float v) {
    ull r; unsigned u = __float_as_uint(v);
    asm("mov.b64 %0, {%1, %1};" : "=l"(r) : "r"(u));
    return r;
}
__device__ __forceinline__ void unpack2(ull p, float &lo, float &hi) {
    unsigned a, b;
    asm("mov.b64 {%0, %1}, %2;" : "=r"(a), "=r"(b) : "l"(p));
    lo = __uint_as_float(a); hi = __uint_as_float(b);
}
__device__ __forceinline__ void fma2(ull &acc, ull a, ull b) {
    asm("fma.rn.f32x2 %0, %1, %2, %0;" : "+l"(acc) : "l"(a), "l"(b));
}
__device__ __forceinline__ float sigf(float x) {
    return __fdividef(1.f, 1.f + __expf(-x));
}
__device__ __forceinline__ float tanhfast(float x) {
    float e = __expf(-2.f * x);
    return __fdividef(1.f - e, 1.f + e);
}

// ------------- cp.async helpers -------------
__device__ __forceinline__ void cp16(unsigned dst, const void* src) {
    asm volatile("cp.async.cg.shared.global [%0], [%1], 16;" :: "r"(dst), "l"(src));
}
__device__ __forceinline__ void cp_commit() { asm volatile("cp.async.commit_group;"); }
template<int N> __device__ __forceinline__ void cp_wait() {
    asm volatile("cp.async.wait_group %0;" :: "n"(N));
}

// stage one 64KB W tile (all 4 gates): thread role g = tid>>7, q = tid&127.
__device__ __forceinline__ void issue_tile(unsigned wtb, const float* __restrict__ gw,
                                           int tile, int q, int g) {
    unsigned dst = wtb + (unsigned)(g*4096 + q*4) * 4u;
    const float4* src = (const float4*)(gw + tile*4096) + q;
#pragma unroll
    for (int j = 0; j < 8; ++j)
        cp16(dst + j*2048u, src + j*128);
    cp_commit();
}

__device__ __forceinline__ void compute_tile(const float* __restrict__ wt,
                                             const ull* __restrict__ h0p,
                                             const ull* __restrict__ h1p,
                                             int c0, ull* acc) {
#pragma unroll 2
    for (int kk = 0; kk < 32; ++kk) {
        ull h0 = h0p[kk], h1 = h1p[kk];
#pragma unroll
        for (int g = 0; g < 4; ++g) {
            const ulonglong2* wp = (const ulonglong2*)(wt + g*4096 + kk*128 + c0);
            ulonglong2 wa = wp[0], wb = wp[1];
            fma2(acc[g*8+0], h0, wa.x); fma2(acc[g*8+1], h0, wa.y);
            fma2(acc[g*8+2], h0, wb.x); fma2(acc[g*8+3], h0, wb.y);
            fma2(acc[g*8+4], h1, wa.x); fma2(acc[g*8+5], h1, wa.y);
            fma2(acc[g*8+6], h1, wb.x); fma2(acc[g*8+7], h1, wb.y);
        }
    }
}

#define INITG(gg, Up, Bp) { \
    float4 u0 = *(const float4*)((Up) + c0); float4 u1 = *(const float4*)((Up) + c0 + 4); \
    float4 v0 = *(const float4*)((Bp) + c0); float4 v1 = *(const float4*)((Bp) + c0 + 4); \
    acc[(gg)*8+0] = pack2(fmaf(xv0,u0.x,v0.x), fmaf(xv0,u0.y,v0.y)); \
    acc[(gg)*8+1] = pack2(fmaf(xv0,u0.z,v0.z), fmaf(xv0,u0.w,v0.w)); \
    acc[(gg)*8+2] = pack2(fmaf(xv0,u1.x,v1.x), fmaf(xv0,u1.y,v1.y)); \
    acc[(gg)*8+3] = pack2(fmaf(xv0,u1.z,v1.z), fmaf(xv0,u1.w,v1.w)); \
    acc[(gg)*8+4] = pack2(fmaf(xv1,u0.x,v0.x), fmaf(xv1,u0.y,v0.y)); \
    acc[(gg)*8+5] = pack2(fmaf(xv1,u0.z,v0.z), fmaf(xv1,u0.w,v0.w)); \
    acc[(gg)*8+6] = pack2(fmaf(xv1,u1.x,v1.x), fmaf(xv1,u1.y,v1.y)); \
    acc[(gg)*8+7] = pack2(fmaf(xv1,u1.z,v1.z), fmaf(xv1,u1.w,v1.w)); }

// full pipelined LSTM cell. precondition: tiles 0,1 of this step already issued.
// postcondition (pf=true): tiles 0,1 of next step issued.
__device__ __forceinline__ void cell_pipe(
    S* s, unsigned wt0, unsigned wt1,
    const float* __restrict__ gw, int q, int g,
    const float* __restrict__ Ujd, const float* __restrict__ Uid,
    const float* __restrict__ Ufd, const float* __restrict__ Uod,
    const float* __restrict__ bjd, const float* __restrict__ bid,
    const float* __restrict__ bfd, const float* __restrict__ bod,
    int lane, int c0, float* c, float* h2, bool pf)
{
    ull acc[32];
    const ull* h0b = s->hdup + (size_t)lane * HS2;
    const ull* h1b = s->hdup + (size_t)(lane + 32) * HS2;
#pragma unroll
    for (int t = 0; t < 4; ++t) {
        if (t < 3 || pf) cp_wait<1>(); else cp_wait<0>();
        __syncthreads();
        if (t == 0) {
            float xv0 = s->xs[lane], xv1 = s->xs[lane + 32];
            INITG(0, Ujd, bjd); INITG(1, Uid, bid);
            INITG(2, Ufd, bfd); INITG(3, Uod, bod);
        }
        const float* wt = (t & 1) ? (const float*)(s->Wt[1]) : (const float*)(s->Wt[0]);
        compute_tile(wt, h0b + t*32, h1b + t*32, c0, acc);
        __syncthreads();
        if (t < 2)      issue_tile(t == 0 ? wt0 : wt1, gw, t + 2, q, g);
        else if (pf)    issue_tile(t == 2 ? wt0 : wt1, gw, t - 2, q, g);
    }
#pragma unroll
    for (int e = 0; e < 8; ++e) {
        int ii = (e >> 2) * 8 + (e & 3) * 2;
        float jl, jh, il, ih, fl, fh, ol, oh;
        unpack2(acc[e],      jl, jh);
        unpack2(acc[8 + e],  il, ih);
        unpack2(acc[16 + e], fl, fh);
        unpack2(acc[24 + e], ol, oh);
        float cl = fmaf(c[ii],   sigf(fl), sigf(il) * tanhfast(jl));
        float ch = fmaf(c[ii+1], sigf(fh), sigf(ih) * tanhfast(jh));
        c[ii] = cl; c[ii+1] = ch;
        h2[ii]   = sigf(ol) * tanhfast(cl);
        h2[ii+1] = sigf(oh) * tanhfast(ch);
    }
}

// ------------- device-wide sense barrier (all 128 CTAs co-resident) -------------
__device__ __forceinline__ void grid_bar() {
    __syncthreads();
    if (threadIdx.x == 0) {
        __threadfence();
        unsigned gen = *(volatile unsigned*)&g_gen;
        if (atomicAdd(&g_cnt, 1u) == NCTA - 1u) {
            g_cnt = 0u;
            __threadfence();
            atomicAdd(&g_gen, 1u);
        } else {
            while (*(volatile unsigned*)&g_gen == gen) __nanosleep(64);
        }
        __threadfence();
    }
    __syncthreads();
}

// ================= encoder: 96 steps persistent =================
__global__ void __launch_bounds__(NTHR, 1) enc_kernel(
    const float* __restrict__ x,
    const float* __restrict__ Uj, const float* __restrict__ Ui,
    const float* __restrict__ Uf, const float* __restrict__ Uo,
    const float* __restrict__ Wj, const float* __restrict__ Wi,
    const float* __restrict__ Wf, const float* __restrict__ Wo,
    const float* __restrict__ bj, const float* __restrict__ bi_,
    const float* __restrict__ bf, const float* __restrict__ bo,
    const float* __restrict__ Fa, const float* __restrict__ Fab,
    const float* __restrict__ Phi_w, const float* __restrict__ Phi_b,
    const float* __restrict__ Fbw,
    float* __restrict__ out)
{
    extern __shared__ char smem_raw[];
    S* s = (S*)smem_raw;

    const int tid = threadIdx.x;
    const int d  = blockIdx.x >> 2;
    const int b0 = (blockIdx.x & 3) * BC;
    const int lane = tid & 31;
    const int w = tid >> 5;
    const int c0 = w * 8;
    const int q = tid & 127;
    const int g = tid >> 7;

    const size_t dHH = (size_t)d * NH * NH;
    const float* gw = (g == 0 ? Wj : g == 1 ? Wi : g == 2 ? Wf : Wo) + dHH;
    const float *Ujd = Uj + d*NH, *Uid = Ui + d*NH, *Ufd = Uf + d*NH, *Uod = Uo + d*NH;
    const float *bjd = bj + d*NH, *bid = bi_ + d*NH, *bfd = bf + d*NH, *bod = bo + d*NH;
    const float fab = Fab[d];

    unsigned wt0 = (unsigned)__cvta_generic_to_shared(s->Wt[0]);
    unsigned wt1 = (unsigned)__cvta_generic_to_shared(s->Wt[1]);

    for (int i = tid; i < BC*HS2; i += NTHR) s->hdup[i] = 0ull;
    if (tid < BC) s->den_s[tid] = 0.f;
    if (tid < NH) s->Fa_s[tid] = Fa[d*NH + tid];

    issue_tile(wt0, gw, 0, q, g);
    issue_tile(wt1, gw, 1, q, g);

    float c[16], num[16], h2[16];
#pragma unroll
    for (int i = 0; i < 16; ++i) { c[i] = 0.f; num[i] = 0.f; }
    __syncthreads();

    for (int t = 0; t < NT; ++t) {
        if (tid < BC) s->xs[tid] = x[((size_t)(b0 + tid)*NT + t)*ND + d];

        cell_pipe(s, wt0, wt1, gw, q, g, Ujd,Uid,Ufd,Uod, bjd,bid,bfd,bod,
                  lane, c0, c, h2, t < NT - 1);

        {
#pragma unroll
            for (int cc = 0; cc < 8; ++cc)
                s->hdup[lane*HS2 + c0 + cc] = dup2(h2[cc]);
#pragma unroll
            for (int cc = 0; cc < 8; ++cc)
                s->hdup[(lane+32)*HS2 + c0 + cc] = dup2(h2[8 + cc]);
            size_t off0 = O_OFS + (((size_t)(b0 + lane)*NT + t)*ND + d)*NH + c0;
            size_t off1 = O_OFS + (((size_t)(b0 + lane + 32)*NT + t)*ND + d)*NH + c0;
            *(float4*)(out + off0)     = make_float4(h2[0],h2[1],h2[2],h2[3]);
            *(float4*)(out + off0 + 4) = make_float4(h2[4],h2[5],h2[6],h2[7]);
            *(float4*)(out + off1)     = make_float4(h2[8],h2[9],h2[10],h2[11]);
            *(float4*)(out + off1 + 4) = make_float4(h2[12],h2[13],h2[14],h2[15]);
        }
        __syncthreads();

        // streaming attention
        {
            int b = tid >> 3, seg = tid & 7;
            const float* hrow = (const float*)&s->hdup[b*HS2];
            float sa = 0.f;
#pragma unroll
            for (int kk = 0; kk < 16; ++kk) {
                int k = seg*16 + kk;
                sa = fmaf(hrow[2*k], s->Fa_s[k], sa);
            }
            sa += __shfl_xor_sync(0xffffffffu, sa, 1);
            sa += __shfl_xor_sync(0xffffffffu, sa, 2);
            sa += __shfl_xor_sync(0xffffffffu, sa, 4);
            if (seg == 0) {
                float e = __expf(tanhfast(sa + fab));
                s->es[b] = e;
                s->den_s[b] += e;
                out[A_OFS + ((size_t)(b0 + b)*NT + t)*ND + d] = e;  // normalized later
            }
        }
        __syncthreads();

        {
            float e0 = s->es[lane], e1 = s->es[lane + 32];
#pragma unroll
            for (int cc = 0; cc < 8; ++cc) {
                num[cc]     = fmaf(e0, h2[cc],     num[cc]);
                num[8 + cc] = fmaf(e1, h2[8 + cc], num[8 + cc]);
            }
        }
    }

    // epilogue: h,c,den; stage g_n into Wt[0]; static mu_g / bt_g
    float* gs = s->Wt[0];
    {
        float inv0 = __fdividef(1.f, s->den_s[lane]);
        float inv1 = __fdividef(1.f, s->den_s[lane + 32]);
        size_t g0 = ((size_t)d*NB + b0 + lane)*NH + c0;
        size_t g1 = ((size_t)d*NB + b0 + lane + 32)*NH + c0;
#pragma unroll
        for (int cc = 0; cc < 8; ++cc) {
            gs[lane*GST + c0 + cc]      = num[cc] * inv0;
            gs[(lane+32)*GST + c0 + cc] = num[8 + cc] * inv1;
            g_h[g0 + cc] = h2[cc];
            g_h[g1 + cc] = h2[8 + cc];
            g_c[g0 + cc] = c[cc];
            g_c[g1 + cc] = c[8 + cc];
        }
    }
    if (tid < BC) g_den[(size_t)(b0 + tid)*ND + d] = s->den_s[tid];
    __syncthreads();

    {   // mu_g = g_n . Phi_top + Phi_b
        int outc = tid & 31, bg = tid >> 5;
        float acc[4];
        float pb = Phi_b[outc];
#pragma unroll
        for (int r = 0; r < 4; ++r) acc[r] = pb;
#pragma unroll 2
        for (int k = 0; k < NH; ++k) {
            float pg = Phi_w[k*NOUT + outc];
#pragma unroll
            for (int r = 0; r < 4; ++r)
                acc[r] = fmaf(gs[(bg*4 + r)*GST + k], pg, acc[r]);
        }
#pragma unroll
        for (int r = 0; r < 4; ++r)
            g_mug[(((size_t)(b0 + bg*4 + r))*ND + d)*NOUT + outc] = acc[r];
    }
    {   // bt_g = g_n . Fbw_top
        int b = tid >> 3, seg = tid & 7;
        float a = 0.f;
#pragma unroll
        for (int kk = 0; kk < 16; ++kk) {
            int k = seg*16 + kk;
            a = fmaf(gs[b*GST + k], Fbw[k], a);
        }
        a += __shfl_xor_sync(0xffffffffu, a, 1);
        a += __shfl_xor_sync(0xffffffffu, a, 2);
        a += __shfl_xor_sync(0xffffffffu, a, 4);
        if (seg == 0) g_btg[(size_t)(b0 + b)*ND + d] = a;
    }
}

// ================= alphas finalize =================
__global__ void alphas_fin_kernel(float* __restrict__ out) {
    int i = blockIdx.x * 256 + threadIdx.x;
    if (i >= A_CNT) return;
    int b = i / (NT*ND);
    int d = i & (ND-1);
    out[A_OFS + i] = __fdividef(out[A_OFS + i], g_den[(size_t)b*ND + d]);
}

// ================= persistent forecast: 24 steps, 1 launch =================
__global__ void __launch_bounds__(NTHR, 1) fc_kernel(
    const float* __restrict__ Uj, const float* __restrict__ Ui,
    const float* __restrict__ Uf, const float* __restrict__ Uo,
    const float* __restrict__ Wj, const float* __restrict__ Wi,
    const float* __restrict__ Wf, const float* __restrict__ Wo,
    const float* __restrict__ bj, const float* __restrict__ bi_,
    const float* __restrict__ bf, const float* __restrict__ bo,
    const float* __restrict__ Phi_w, const float* __restrict__ Fbw,
    const float* __restrict__ Fbb,
    const float* __restrict__ proj_w, const float* __restrict__ proj_b,
    float* __restrict__ out)
{
    extern __shared__ char smem_raw[];
    S* s = (S*)smem_raw;

    const int tid = threadIdx.x;
    const int d  = blockIdx.x >> 2;
    const int b0 = (blockIdx.x & 3) * BC;
    const int lane = tid & 31;
    const int w = tid >> 5;
    const int c0 = w * 8;
    const int q = tid & 127;
    const int g = tid >> 7;
    const int outc = tid & 31, bg = tid >> 5;
    const int bb_ = tid >> 3, seg = tid & 7;

    const size_t dHH = (size_t)d * NH * NH;
    const float* gw = (g == 0 ? Wj : g == 1 ? Wi : g == 2 ? Wf : Wo) + dHH;
    const float *Ujd = Uj + d*NH, *Uid = Ui + d*NH, *Ufd = Uf + d*NH, *Uod = Uo + d*NH;
    const float *bjd = bj + d*NH, *bid = bi_ + d*NH, *bfd = bf + d*NH, *bod = bo + d*NH;

    unsigned wt0 = (unsigned)__cvta_generic_to_shared(s->Wt[0]);
    unsigned wt1 = (unsigned)__cvta_generic_to_shared(s->Wt[1]);

    issue_tile(wt0, gw, 0, q, g);
    issue_tile(wt1, gw, 1, q, g);

    // resident state init
    for (int i = tid; i < BC*NH; i += NTHR) {
        int b = i >> 7, k = i & 127;
        s->hdup[b*HS2 + k] = dup2(g_h[((size_t)d*NB + b0 + b)*NH + k]);
    }
    for (int i = tid; i < NH*NOUT; i += NTHR)
        s->phi_s[i] = Phi_w[(NH + (i >> 5))*NOUT + (i & 31)];
    if (tid < NH) s->fbw_s[tid] = Fbw[NH + tid];

    float c[16], h2[16];
    {
        size_t g0 = ((size_t)d*NB + b0 + lane)*NH + c0;
        size_t g1 = ((size_t)d*NB + b0 + lane + 32)*NH + c0;
        float4 a0 = *(const float4*)(g_c + g0);
        float4 a1 = *(const float4*)(g_c + g0 + 4);
        float4 a2 = *(const float4*)(g_c + g1);
        float4 a3 = *(const float4*)(g_c + g1 + 4);
        c[0]=a0.x; c[1]=a0.y; c[2]=a0.z; c[3]=a0.w;
        c[4]=a1.x; c[5]=a1.y; c[6]=a1.z; c[7]=a1.w;
        c[8]=a2.x; c[9]=a2.y; c[10]=a2.z; c[11]=a2.w;
        c[12]=a3.x; c[13]=a3.y; c[14]=a3.z; c[15]=a3.w;
    }
    float mug[4];
#pragma unroll
    for (int r = 0; r < 4; ++r)
        mug[r] = g_mug[(((size_t)(b0 + bg*4 + r))*ND + d)*NOUT + outc];
    const float btg = g_btg[(size_t)(b0 + bb_)*ND + d] + Fbb[0];
    __syncthreads();

    for (int f = 0; f < NF; ++f) {
        const int p = f & 1;

        // mu = mu_g + h . Phi_bot
        {
            float acc[4];
#pragma unroll
            for (int r = 0; r < 4; ++r) acc[r] = mug[r];
#pragma unroll 2
            for (int k = 0; k < NH; ++k) {
                float ph = s->phi_s[k*NOUT + outc];
#pragma unroll
                for (int r = 0; r < 4; ++r) {
                    float hv = *(const float*)&s->hdup[(bg*4 + r)*HS2 + k];
                    acc[r] = fmaf(hv, ph, acc[r]);
                }
            }
#pragma unroll
            for (int r = 0; r < 4; ++r)
                g_mu2[p][(((size_t)(b0 + bg*4 + r))*ND + d)*NOUT + outc] = acc[r];
        }
        // bt = exp(tanh(bt_g + h . Fbw_bot + Fbb))
        {
            const float* hrow = (const float*)&s->hdup[bb_*HS2];
            float a = 0.f;
#pragma unroll
            for (int kk = 0; kk < 16; ++kk) {
                int k = seg*16 + kk;
                a = fmaf(hrow[2*k], s->fbw_s[k], a);
            }
            a += __shfl_xor_sync(0xffffffffu, a, 1);
            a += __shfl_xor_sync(0xffffffffu, a, 2);
            a += __shfl_xor_sync(0xffffffffu, a, 4);
            if (seg == 0)
                g_bt2[p][(size_t)(b0 + bb_)*ND + d] = __expf(tanhfast(a + btg));
        }
        __threadfence();
        grid_bar();

        // reduce over D: betas, y, prev -> xs
#pragma unroll
        for (int rr = 0; rr < 4; ++rr) {
            int b = w*4 + rr;
            float bt = g_bt2[p][(size_t)(b0 + b)*ND + lane];
            float ssum = bt;
#pragma unroll
            for (int o = 16; o > 0; o >>= 1)
                ssum += __shfl_xor_sync(0xffffffffu, ssum, o);
            float beta = __fdividef(bt, ssum);
            if (d == 0)
                out[B_OFS + ((size_t)(b0 + b)*NF + f)*ND + lane] = beta;

            float y = 0.f;
            const float* mup = g_mu2[p] + ((size_t)(b0 + b)*ND)*NOUT + lane;
#pragma unroll
            for (int d2 = 0; d2 < ND; ++d2)
                y = fmaf(__shfl_sync(0xffffffffu, beta, d2), mup[d2*NOUT], y);
            if (d == 0)
                out[((size_t)(b0 + b)*NF + f)*NOUT + lane] = y;

            float pr = y * proj_w[lane*ND + d];
#pragma unroll
            for (int o = 16; o > 0; o >>= 1)
                pr += __shfl_xor_sync(0xffffffffu, pr, o);
            if (lane == 0) s->xs[b] = pr + proj_b[d];
        }
        if (f == NF - 1) break;

        cell_pipe(s, wt0, wt1, gw, q, g, Ujd,Uid,Ufd,Uod, bjd,bid,bfd,bod,
                  lane, c0, c, h2, f < NF - 2);

#pragma unroll
        for (int cc = 0; cc < 8; ++cc) {
            s->hdup[lane*HS2 + c0 + cc]      = dup2(h2[cc]);
            s->hdup[(lane+32)*HS2 + c0 + cc] = dup2(h2[8 + cc]);
        }
        __syncthreads();
    }
}

// ================= launch =================
extern "C" void kernel_launch(void* const* d_in, const int* in_sizes, int n_in,
                              void* d_out, int out_size) {
    const float* x    = (const float*)d_in[0];
    const float* Uj   = (const float*)d_in[1];
    const float* Ui   = (const float*)d_in[2];
    const float* Uf   = (const float*)d_in[3];
    const float* Uo   = (const float*)d_in[4];
    const float* Wj   = (const float*)d_in[5];
    const float* Wi   = (const float*)d_in[6];
    const float* Wf   = (const float*)d_in[7];
    const float* Wo   = (const float*)d_in[8];
    const float* bj   = (const float*)d_in[9];
    const float* bi   = (const float*)d_in[10];
    const float* bf   = (const float*)d_in[11];
    const float* bo   = (const float*)d_in[12];
    const float* Fa   = (const float*)d_in[13];
    const float* Fab  = (const float*)d_in[14];
    const float* Fbw  = (const float*)d_in[15];
    const float* Fbb  = (const float*)d_in[16];
    const float* Phw  = (const float*)d_in[17];
    const float* Phb  = (const float*)d_in[18];
    const float* prw  = (const float*)d_in[19];
    const float* prb  = (const float*)d_in[20];
    float* out = (float*)d_out;

    int smem = (int)sizeof(S);
    cudaFuncSetAttribute(enc_kernel, cudaFuncAttributeMaxDynamicSharedMemorySize, smem);
    cudaFuncSetAttribute(fc_kernel,  cudaFuncAttributeMaxDynamicSharedMemorySize, smem);

    enc_kernel<<<NCTA, NTHR, smem>>>(x, Uj,Ui,Uf,Uo, Wj,Wi,Wf,Wo, bj,bi,bf,bo,
                                     Fa, Fab, Phw, Phb, Fbw, out);
    alphas_fin_kernel<<<(A_CNT + 255)/256, 256>>>(out);
    fc_kernel<<<NCTA, NTHR, smem>>>(Uj,Ui,Uf,Uo, Wj,Wi,Wf,Wo, bj,bi,bf,bo,
                                    Phw, Fbw, Fbb, prw, prb, out);
}

// round 7
// speedup vs baseline: 2.6907x; 1.0453x over previous
#include <cuda_runtime.h>

#define NB 256
#define NT 96
#define ND 32
#define NH 128
#define NOUT 32
#define NF 24
#define BC 64
#define NCTA 128
#define NTHR 512
#define HS2 129   // ull stride for hdup rows (conflict-free LDS.64)
#define GST 130   // float stride for gn staging rows

#define F_CNT (NB*NF*NOUT)
#define A_OFS F_CNT
#define A_CNT (NB*NT*ND)
#define B_OFS (A_OFS + A_CNT)
#define O_OFS (B_OFS + NB*NF*ND)

typedef unsigned long long ull;

// ------------- scratch (no allocs allowed) -------------
__device__ float g_h[ND*NB*NH];
__device__ float g_c[ND*NB*NH];
__device__ float g_den[NB*ND];
__device__ float g_mug[NB*ND*NOUT];   // static part of mu
__device__ float g_btg[NB*ND];        // static part of bt argument
__device__ float g_mu2[2][NB*ND*NOUT];
__device__ float g_bt2[2][NB*ND];
__device__ unsigned g_cnt;
__device__ unsigned g_gen;

struct S {
    float Wt[2][4*32*128];   // double-buffered W tile [gate][kk][col], 2 x 64KB
    ull   hdup[BC*HS2];      // h duplicated into both f32x2 lanes
    float phi_s[NH*NOUT];    // Phi_w bottom half (h part)
    float fbw_s[NH];         // F_beta_w bottom half
    float part[BC*17];       // attention partials [row][warp]
    float xs[BC];
    float es[BC];
    float den_s[BC];
};

// ------------- packed f32x2 helpers -------------
__device__ __forceinline__ ull pack2(float lo, float hi) {
    ull r;
    asm("mov.b64 %0, {%1, %2};" : "=l"(r)
        : "r"(__float_as_uint(lo)), "r"(__float_as_uint(hi)));
    return r;
}
__device__ __forceinline__ ull dup2(float v) {
    ull r; unsigned u = __float_as_uint(v);
    asm("mov.b64 %0, {%1, %1};" : "=l"(r) : "r"(u));
    return r;
}
__device__ __forceinline__ void unpack2(ull p, float &lo, float &hi) {
    unsigned a, b;
    asm("mov.b64 {%0, %1}, %2;" : "=r"(a), "=r"(b) : "l"(p));
    lo = __uint_as_float(a); hi = __uint_as_float(b);
}
__device__ __forceinline__ void fma2(ull &acc, ull a, ull b) {
    asm("fma.rn.f32x2 %0, %1, %2, %0;" : "+l"(acc) : "l"(a), "l"(b));
}
__device__ __forceinline__ float sigf(float x) {
    return __fdividef(1.f, 1.f + __expf(-x));
}
__device__ __forceinline__ float tanhfast(float x) {
    float e = __expf(-2.f * x);
    return __fdividef(1.f - e, 1.f + e);
}

// ------------- cp.async helpers -------------
__device__ __forceinline__ void cp16(unsigned dst, const void* src) {
    asm volatile("cp.async.cg.shared.global [%0], [%1], 16;" :: "r"(dst), "l"(src));
}
__device__ __forceinline__ void cp_commit() { asm volatile("cp.async.commit_group;"); }
template<int N> __device__ __forceinline__ void cp_wait() {
    asm volatile("cp.async.wait_group %0;" :: "n"(N));
}

// stage one 64KB W tile (all 4 gates): thread role g = tid>>7, q = tid&127.
__device__ __forceinline__ void issue_tile(unsigned wtb, const float* __restrict__ gw,
                                           int tile, int q, int g) {
    unsigned dst = wtb + (unsigned)(g*4096 + q*4) * 4u;
    const float4* src = (const float4*)(gw + tile*4096) + q;
#pragma unroll
    for (int j = 0; j < 8; ++j)
        cp16(dst + j*2048u, src + j*128);
    cp_commit();
}

// software-pipelined tile compute: preload next gate's W / next kk's h
// before current gate's 8 FFMA2s. Tail over-reads stay inside valid smem.
__device__ __forceinline__ void compute_tile(const float* __restrict__ wt,
                                             const ull* __restrict__ h0p,
                                             const ull* __restrict__ h1p,
                                             int c0, ull* acc) {
    const float* base = wt + c0;
    ulonglong2 wa = *(const ulonglong2*)(base);
    ulonglong2 wb = *(const ulonglong2*)(base + 4);
    ull h0 = h0p[0], h1 = h1p[0];
#pragma unroll 4
    for (int kk = 0; kk < 32; ++kk) {
        ull h0n = h0p[kk + 1], h1n = h1p[kk + 1];
#pragma unroll
        for (int g = 0; g < 4; ++g) {
            const float* nb = base + (g == 3 ? (kk + 1)*128 : (g + 1)*4096 + kk*128);
            ulonglong2 wan = *(const ulonglong2*)(nb);
            ulonglong2 wbn = *(const ulonglong2*)(nb + 4);
            fma2(acc[g*8+0], h0, wa.x); fma2(acc[g*8+1], h0, wa.y);
            fma2(acc[g*8+2], h0, wb.x); fma2(acc[g*8+3], h0, wb.y);
            fma2(acc[g*8+4], h1, wa.x); fma2(acc[g*8+5], h1, wa.y);
            fma2(acc[g*8+6], h1, wb.x); fma2(acc[g*8+7], h1, wb.y);
            wa = wan; wb = wbn;
        }
        h0 = h0n; h1 = h1n;
    }
}

#define INITG(gg, Up, Bp) { \
    float4 u0 = *(const float4*)((Up) + c0); float4 u1 = *(const float4*)((Up) + c0 + 4); \
    float4 v0 = *(const float4*)((Bp) + c0); float4 v1 = *(const float4*)((Bp) + c0 + 4); \
    acc[(gg)*8+0] = pack2(fmaf(xv0,u0.x,v0.x), fmaf(xv0,u0.y,v0.y)); \
    acc[(gg)*8+1] = pack2(fmaf(xv0,u0.z,v0.z), fmaf(xv0,u0.w,v0.w)); \
    acc[(gg)*8+2] = pack2(fmaf(xv0,u1.x,v1.x), fmaf(xv0,u1.y,v1.y)); \
    acc[(gg)*8+3] = pack2(fmaf(xv0,u1.z,v1.z), fmaf(xv0,u1.w,v1.w)); \
    acc[(gg)*8+4] = pack2(fmaf(xv1,u0.x,v0.x), fmaf(xv1,u0.y,v0.y)); \
    acc[(gg)*8+5] = pack2(fmaf(xv1,u0.z,v0.z), fmaf(xv1,u0.w,v0.w)); \
    acc[(gg)*8+6] = pack2(fmaf(xv1,u1.x,v1.x), fmaf(xv1,u1.y,v1.y)); \
    acc[(gg)*8+7] = pack2(fmaf(xv1,u1.z,v1.z), fmaf(xv1,u1.w,v1.w)); }

// full pipelined LSTM cell. precondition: tiles 0,1 of this step already issued.
// postcondition (pf=true): tiles 0,1 of next step issued.
__device__ __forceinline__ void cell_pipe(
    S* s, unsigned wt0, unsigned wt1,
    const float* __restrict__ gw, int q, int g,
    const float* __restrict__ Ujd, const float* __restrict__ Uid,
    const float* __restrict__ Ufd, const float* __restrict__ Uod,
    const float* __restrict__ bjd, const float* __restrict__ bid,
    const float* __restrict__ bfd, const float* __restrict__ bod,
    int lane, int c0, float* c, float* h2, bool pf)
{
    ull acc[32];
    __syncthreads();                        // xs visible
    {
        float xv0 = s->xs[lane], xv1 = s->xs[lane + 32];
        INITG(0, Ujd, bjd); INITG(1, Uid, bid);
        INITG(2, Ufd, bfd); INITG(3, Uod, bod);
    }
    const ull* h0b = s->hdup + (size_t)lane * HS2;
    const ull* h1b = s->hdup + (size_t)(lane + 32) * HS2;
#pragma unroll 1
    for (int t = 0; t < 4; ++t) {
        if (t < 3 || pf) cp_wait<1>(); else cp_wait<0>();
        __syncthreads();
        const float* wt = (t & 1) ? (const float*)(s->Wt[1]) : (const float*)(s->Wt[0]);
        compute_tile(wt, h0b + t*32, h1b + t*32, c0, acc);
        __syncthreads();
        if (t < 2 || pf) issue_tile((t & 1) ? wt1 : wt0, gw, (t + 2) & 3, q, g);
    }
#pragma unroll
    for (int e = 0; e < 8; ++e) {
        int ii = (e >> 2) * 8 + (e & 3) * 2;
        float jl, jh, il, ih, fl, fh, ol, oh;
        unpack2(acc[e],      jl, jh);
        unpack2(acc[8 + e],  il, ih);
        unpack2(acc[16 + e], fl, fh);
        unpack2(acc[24 + e], ol, oh);
        float cl = fmaf(c[ii],   sigf(fl), sigf(il) * tanhfast(jl));
        float ch = fmaf(c[ii+1], sigf(fh), sigf(ih) * tanhfast(jh));
        c[ii] = cl; c[ii+1] = ch;
        h2[ii]   = sigf(ol) * tanhfast(cl);
        h2[ii+1] = sigf(oh) * tanhfast(ch);
    }
}

// ------------- device-wide sense barrier (all 128 CTAs co-resident) -------------
__device__ __forceinline__ void grid_bar() {
    __syncthreads();
    if (threadIdx.x == 0) {
        __threadfence();
        unsigned gen = *(volatile unsigned*)&g_gen;
        if (atomicAdd(&g_cnt, 1u) == NCTA - 1u) {
            g_cnt = 0u;
            __threadfence();
            atomicAdd(&g_gen, 1u);
        } else {
            while (*(volatile unsigned*)&g_gen == gen) __nanosleep(64);
        }
        __threadfence();
    }
    __syncthreads();
}

// ================= encoder: 96 steps persistent =================
__global__ void __launch_bounds__(NTHR, 1) enc_kernel(
    const float* __restrict__ x,
    const float* __restrict__ Uj, const float* __restrict__ Ui,
    const float* __restrict__ Uf, const float* __restrict__ Uo,
    const float* __restrict__ Wj, const float* __restrict__ Wi,
    const float* __restrict__ Wf, const float* __restrict__ Wo,
    const float* __restrict__ bj, const float* __restrict__ bi_,
    const float* __restrict__ bf, const float* __restrict__ bo,
    const float* __restrict__ Fa, const float* __restrict__ Fab,
    const float* __restrict__ Phi_w, const float* __restrict__ Phi_b,
    const float* __restrict__ Fbw,
    float* __restrict__ out)
{
    extern __shared__ char smem_raw[];
    S* s = (S*)smem_raw;

    const int tid = threadIdx.x;
    const int d  = blockIdx.x >> 2;
    const int b0 = (blockIdx.x & 3) * BC;
    const int lane = tid & 31;
    const int w = tid >> 5;
    const int c0 = w * 8;
    const int q = tid & 127;
    const int g = tid >> 7;

    const size_t dHH = (size_t)d * NH * NH;
    const float* gw = (g == 0 ? Wj : g == 1 ? Wi : g == 2 ? Wf : Wo) + dHH;
    const float *Ujd = Uj + d*NH, *Uid = Ui + d*NH, *Ufd = Uf + d*NH, *Uod = Uo + d*NH;
    const float *bjd = bj + d*NH, *bid = bi_ + d*NH, *bfd = bf + d*NH, *bod = bo + d*NH;
    const float fab = Fab[d];

    unsigned wt0 = (unsigned)__cvta_generic_to_shared(s->Wt[0]);
    unsigned wt1 = (unsigned)__cvta_generic_to_shared(s->Wt[1]);

    float fa[8];
#pragma unroll
    for (int cc = 0; cc < 8; ++cc) fa[cc] = Fa[(size_t)d*NH + c0 + cc];

    for (int i = tid; i < BC*HS2; i += NTHR) s->hdup[i] = 0ull;
    if (tid < BC) s->den_s[tid] = 0.f;

    issue_tile(wt0, gw, 0, q, g);
    issue_tile(wt1, gw, 1, q, g);

    float c[16], num[16], h2[16];
#pragma unroll
    for (int i = 0; i < 16; ++i) { c[i] = 0.f; num[i] = 0.f; }

    for (int t = 0; t < NT; ++t) {
        if (tid < BC) s->xs[tid] = x[((size_t)(b0 + tid)*NT + t)*ND + d];

        cell_pipe(s, wt0, wt1, gw, q, g, Ujd,Uid,Ufd,Uod, bjd,bid,bfd,bod,
                  lane, c0, c, h2, t < NT - 1);

        // attention partials from registers + hdup store + outputs
        {
            float p0 = 0.f, p1 = 0.f;
#pragma unroll
            for (int cc = 0; cc < 8; ++cc) {
                p0 = fmaf(h2[cc],     fa[cc], p0);
                p1 = fmaf(h2[8 + cc], fa[cc], p1);
            }
            s->part[lane*17 + w]        = p0;
            s->part[(lane + 32)*17 + w] = p1;
#pragma unroll
            for (int cc = 0; cc < 8; ++cc)
                s->hdup[lane*HS2 + c0 + cc] = dup2(h2[cc]);
#pragma unroll
            for (int cc = 0; cc < 8; ++cc)
                s->hdup[(lane+32)*HS2 + c0 + cc] = dup2(h2[8 + cc]);
            size_t off0 = O_OFS + (((size_t)(b0 + lane)*NT + t)*ND + d)*NH + c0;
            size_t off1 = O_OFS + (((size_t)(b0 + lane + 32)*NT + t)*ND + d)*NH + c0;
            *(float4*)(out + off0)     = make_float4(h2[0],h2[1],h2[2],h2[3]);
            *(float4*)(out + off0 + 4) = make_float4(h2[4],h2[5],h2[6],h2[7]);
            *(float4*)(out + off1)     = make_float4(h2[8],h2[9],h2[10],h2[11]);
            *(float4*)(out + off1 + 4) = make_float4(h2[12],h2[13],h2[14],h2[15]);
        }
        __syncthreads();

        // finalize attention: 8 threads per row reduce 16 partials
        {
            int b = tid >> 3, seg = tid & 7;
            float v = s->part[b*17 + 2*seg] + s->part[b*17 + 2*seg + 1];
            v += __shfl_xor_sync(0xffffffffu, v, 1);
            v += __shfl_xor_sync(0xffffffffu, v, 2);
            v += __shfl_xor_sync(0xffffffffu, v, 4);
            if (seg == 0) {
                float e = __expf(tanhfast(v + fab));
                s->es[b] = e;
                s->den_s[b] += e;
                out[A_OFS + ((size_t)(b0 + b)*NT + t)*ND + d] = e;  // normalized later
            }
        }
        __syncthreads();

        {
            float e0 = s->es[lane], e1 = s->es[lane + 32];
#pragma unroll
            for (int cc = 0; cc < 8; ++cc) {
                num[cc]     = fmaf(e0, h2[cc],     num[cc]);
                num[8 + cc] = fmaf(e1, h2[8 + cc], num[8 + cc]);
            }
        }
    }

    // epilogue: h,c,den; stage g_n into Wt[0]; static mu_g / bt_g
    float* gs = s->Wt[0];
    {
        float inv0 = __fdividef(1.f, s->den_s[lane]);
        float inv1 = __fdividef(1.f, s->den_s[lane + 32]);
        size_t g0 = ((size_t)d*NB + b0 + lane)*NH + c0;
        size_t g1 = ((size_t)d*NB + b0 + lane + 32)*NH + c0;
#pragma unroll
        for (int cc = 0; cc < 8; ++cc) {
            gs[lane*GST + c0 + cc]      = num[cc] * inv0;
            gs[(lane+32)*GST + c0 + cc] = num[8 + cc] * inv1;
            g_h[g0 + cc] = h2[cc];
            g_h[g1 + cc] = h2[8 + cc];
            g_c[g0 + cc] = c[cc];
            g_c[g1 + cc] = c[8 + cc];
        }
    }
    if (tid < BC) g_den[(size_t)(b0 + tid)*ND + d] = s->den_s[tid];
    __syncthreads();

    {   // mu_g = g_n . Phi_top + Phi_b
        int outc = tid & 31, bg = tid >> 5;
        float acc[4];
        float pb = Phi_b[outc];
#pragma unroll
        for (int r = 0; r < 4; ++r) acc[r] = pb;
#pragma unroll 2
        for (int k = 0; k < NH; ++k) {
            float pg = Phi_w[k*NOUT + outc];
#pragma unroll
            for (int r = 0; r < 4; ++r)
                acc[r] = fmaf(gs[(bg*4 + r)*GST + k], pg, acc[r]);
        }
#pragma unroll
        for (int r = 0; r < 4; ++r)
            g_mug[(((size_t)(b0 + bg*4 + r))*ND + d)*NOUT + outc] = acc[r];
    }
    {   // bt_g = g_n . Fbw_top
        int b = tid >> 3, seg = tid & 7;
        float a = 0.f;
#pragma unroll
        for (int kk = 0; kk < 16; ++kk) {
            int k = seg*16 + kk;
            a = fmaf(gs[b*GST + k], Fbw[k], a);
        }
        a += __shfl_xor_sync(0xffffffffu, a, 1);
        a += __shfl_xor_sync(0xffffffffu, a, 2);
        a += __shfl_xor_sync(0xffffffffu, a, 4);
        if (seg == 0) g_btg[(size_t)(b0 + b)*ND + d] = a;
    }
}

// ================= alphas finalize =================
__global__ void alphas_fin_kernel(float* __restrict__ out) {
    int i = blockIdx.x * 256 + threadIdx.x;
    if (i >= A_CNT) return;
    int b = i / (NT*ND);
    int d = i & (ND-1);
    out[A_OFS + i] = __fdividef(out[A_OFS + i], g_den[(size_t)b*ND + d]);
}

// ================= persistent forecast: 24 steps, 1 launch =================
__global__ void __launch_bounds__(NTHR, 1) fc_kernel(
    const float* __restrict__ Uj, const float* __restrict__ Ui,
    const float* __restrict__ Uf, const float* __restrict__ Uo,
    const float* __restrict__ Wj, const float* __restrict__ Wi,
    const float* __restrict__ Wf, const float* __restrict__ Wo,
    const float* __restrict__ bj, const float* __restrict__ bi_,
    const float* __restrict__ bf, const float* __restrict__ bo,
    const float* __restrict__ Phi_w, const float* __restrict__ Fbw,
    const float* __restrict__ Fbb,
    const float* __restrict__ proj_w, const float* __restrict__ proj_b,
    float* __restrict__ out)
{
    extern __shared__ char smem_raw[];
    S* s = (S*)smem_raw;

    const int tid = threadIdx.x;
    const int d  = blockIdx.x >> 2;
    const int b0 = (blockIdx.x & 3) * BC;
    const int lane = tid & 31;
    const int w = tid >> 5;
    const int c0 = w * 8;
    const int q = tid & 127;
    const int g = tid >> 7;
    const int outc = tid & 31, bg = tid >> 5;
    const int bb_ = tid >> 3, seg = tid & 7;

    const size_t dHH = (size_t)d * NH * NH;
    const float* gw = (g == 0 ? Wj : g == 1 ? Wi : g == 2 ? Wf : Wo) + dHH;
    const float *Ujd = Uj + d*NH, *Uid = Ui + d*NH, *Ufd = Uf + d*NH, *Uod = Uo + d*NH;
    const float *bjd = bj + d*NH, *bid = bi_ + d*NH, *bfd = bf + d*NH, *bod = bo + d*NH;

    unsigned wt0 = (unsigned)__cvta_generic_to_shared(s->Wt[0]);
    unsigned wt1 = (unsigned)__cvta_generic_to_shared(s->Wt[1]);

    issue_tile(wt0, gw, 0, q, g);
    issue_tile(wt1, gw, 1, q, g);

    // resident state init
    for (int i = tid; i < BC*NH; i += NTHR) {
        int b = i >> 7, k = i & 127;
        s->hdup[b*HS2 + k] = dup2(g_h[((size_t)d*NB + b0 + b)*NH + k]);
    }
    for (int i = tid; i < NH*NOUT; i += NTHR)
        s->phi_s[i] = Phi_w[(NH + (i >> 5))*NOUT + (i & 31)];
    if (tid < NH) s->fbw_s[tid] = Fbw[NH + tid];

    float c[16], h2[16];
    {
        size_t g0 = ((size_t)d*NB + b0 + lane)*NH + c0;
        size_t g1 = ((size_t)d*NB + b0 + lane + 32)*NH + c0;
        float4 a0 = *(const float4*)(g_c + g0);
        float4 a1 = *(const float4*)(g_c + g0 + 4);
        float4 a2 = *(const float4*)(g_c + g1);
        float4 a3 = *(const float4*)(g_c + g1 + 4);
        c[0]=a0.x; c[1]=a0.y; c[2]=a0.z; c[3]=a0.w;
        c[4]=a1.x; c[5]=a1.y; c[6]=a1.z; c[7]=a1.w;
        c[8]=a2.x; c[9]=a2.y; c[10]=a2.z; c[11]=a2.w;
        c[12]=a3.x; c[13]=a3.y; c[14]=a3.z; c[15]=a3.w;
    }
    float mug[4];
#pragma unroll
    for (int r = 0; r < 4; ++r)
        mug[r] = g_mug[(((size_t)(b0 + bg*4 + r))*ND + d)*NOUT + outc];
    const float btg = g_btg[(size_t)(b0 + bb_)*ND + d] + Fbb[0];
    __syncthreads();

    for (int f = 0; f < NF; ++f) {
        const int p = f & 1;

        // mu = mu_g + h . Phi_bot
        {
            float acc[4];
#pragma unroll
            for (int r = 0; r < 4; ++r) acc[r] = mug[r];
#pragma unroll 2
            for (int k = 0; k < NH; ++k) {
                float ph = s->phi_s[k*NOUT + outc];
#pragma unroll
                for (int r = 0; r < 4; ++r) {
                    float hv = *(const float*)&s->hdup[(bg*4 + r)*HS2 + k];
                    acc[r] = fmaf(hv, ph, acc[r]);
                }
            }
#pragma unroll
            for (int r = 0; r < 4; ++r)
                g_mu2[p][(((size_t)(b0 + bg*4 + r))*ND + d)*NOUT + outc] = acc[r];
        }
        // bt = exp(tanh(bt_g + h . Fbw_bot + Fbb))
        {
            const float* hrow = (const float*)&s->hdup[bb_*HS2];
            float a = 0.f;
#pragma unroll
            for (int kk = 0; kk < 16; ++kk) {
                int k = seg*16 + kk;
                a = fmaf(hrow[2*k], s->fbw_s[k], a);
            }
            a += __shfl_xor_sync(0xffffffffu, a, 1);
            a += __shfl_xor_sync(0xffffffffu, a, 2);
            a += __shfl_xor_sync(0xffffffffu, a, 4);
            if (seg == 0)
                g_bt2[p][(size_t)(b0 + bb_)*ND + d] = __expf(tanhfast(a + btg));
        }
        __threadfence();
        grid_bar();

        // reduce over D: betas, y, prev -> xs
#pragma unroll
        for (int rr = 0; rr < 4; ++rr) {
            int b = w*4 + rr;
            float bt = g_bt2[p][(size_t)(b0 + b)*ND + lane];
            float ssum = bt;
#pragma unroll
            for (int o = 16; o > 0; o >>= 1)
                ssum += __shfl_xor_sync(0xffffffffu, ssum, o);
            float beta = __fdividef(bt, ssum);
            if (d == 0)
                out[B_OFS + ((size_t)(b0 + b)*NF + f)*ND + lane] = beta;

            float y = 0.f;
            const float* mup = g_mu2[p] + ((size_t)(b0 + b)*ND)*NOUT + lane;
#pragma unroll
            for (int d2 = 0; d2 < ND; ++d2)
                y = fmaf(__shfl_sync(0xffffffffu, beta, d2), mup[d2*NOUT], y);
            if (d == 0)
                out[((size_t)(b0 + b)*NF + f)*NOUT + lane] = y;

            float pr = y * proj_w[lane*ND + d];
#pragma unroll
            for (int o = 16; o > 0; o >>= 1)
                pr += __shfl_xor_sync(0xffffffffu, pr, o);
            if (lane == 0) s->xs[b] = pr + proj_b[d];
        }
        if (f == NF - 1) break;

        cell_pipe(s, wt0, wt1, gw, q, g, Ujd,Uid,Ufd,Uod, bjd,bid,bfd,bod,
                  lane, c0, c, h2, f < NF - 2);

#pragma unroll
        for (int cc = 0; cc < 8; ++cc) {
            s->hdup[lane*HS2 + c0 + cc]      = dup2(h2[cc]);
            s->hdup[(lane+32)*HS2 + c0 + cc] = dup2(h2[8 + cc]);
        }
        __syncthreads();
    }
}

// ================= launch =================
extern "C" void kernel_launch(void* const* d_in, const int* in_sizes, int n_in,
                              void* d_out, int out_size) {
    const float* x    = (const float*)d_in[0];
    const float* Uj   = (const float*)d_in[1];
    const float* Ui   = (const float*)d_in[2];
    const float* Uf   = (const float*)d_in[3];
    const float* Uo   = (const float*)d_in[4];
    const float* Wj   = (const float*)d_in[5];
    const float* Wi   = (const float*)d_in[6];
    const float* Wf   = (const float*)d_in[7];
    const float* Wo   = (const float*)d_in[8];
    const float* bj   = (const float*)d_in[9];
    const float* bi   = (const float*)d_in[10];
    const float* bf   = (const float*)d_in[11];
    const float* bo   = (const float*)d_in[12];
    const float* Fa   = (const float*)d_in[13];
    const float* Fab  = (const float*)d_in[14];
    const float* Fbw  = (const float*)d_in[15];
    const float* Fbb  = (const float*)d_in[16];
    const float* Phw  = (const float*)d_in[17];
    const float* Phb  = (const float*)d_in[18];
    const float* prw  = (const float*)d_in[19];
    const float* prb  = (const float*)d_in[20];
    float* out = (float*)d_out;

    int smem = (int)sizeof(S);
    cudaFuncSetAttribute(enc_kernel, cudaFuncAttributeMaxDynamicSharedMemorySize, smem);
    cudaFuncSetAttribute(fc_kernel,  cudaFuncAttributeMaxDynamicSharedMemorySize, smem);

    enc_kernel<<<NCTA, NTHR, smem>>>(x, Uj,Ui,Uf,Uo, Wj,Wi,Wf,Wo, bj,bi,bf,bo,
                                     Fa, Fab, Phw, Phb, Fbw, out);
    alphas_fin_kernel<<<(A_CNT + 255)/256, 256>>>(out);
    fc_kernel<<<NCTA, NTHR, smem>>>(Uj,Ui,Uf,Uo, Wj,Wi,Wf,Wo, bj,bi,bf,bo,
                                    Phw, Fbw, Fbb, prw, prb, out);
}